// round 4
// baseline (speedup 1.0000x reference)
#include <cuda_runtime.h>
#include <math.h>

#define N_SAMPLES   65536
#define N_FRAMES    128
#define NUM_COEFF   6
#define NUM_ACTIVE  7
#define NSER        7
#define DEPTH       3        // payload pipeline depth (chunks in flight)

// ---------------- device scratch (no allocation allowed) ----------------
__device__ float  g_y[NSER][N_FRAMES];
__device__ float  g_M[NSER][N_FRAMES];
__device__ float4 g_AB[N_SAMPLES * 2];   // [2t]=v0..v3, [2t+1]=v4,v5,v6,x
__device__ int    g_P[N_SAMPLES];        // base index = t - 1 - z
__device__ int    g_minz;
__device__ int    g_maxz;
__device__ int    g_flag;

// ---------------- kernel A: coeff frames + spline tridiagonal solves ----------------
__global__ void prep_kernel(const float* __restrict__ delay,
                            const float* __restrict__ raw_gain,
                            const float* __restrict__ raw_coeff)
{
    __shared__ float s_y[NSER][N_FRAMES];
    __shared__ float s_cp[N_FRAMES];
    __shared__ float s_d[NSER][N_FRAMES];
    __shared__ float s_gain;

    const int tid = threadIdx.x;

    if (tid == 0) {
        s_gain = 1.0f / (1.0f + expf(-raw_gain[0]));
        g_minz = 0x7fffffff;
        g_maxz = 0;
        g_flag = 0;
        float c = 0.25f;
        s_cp[0] = c;
        for (int i = 1; i < N_FRAMES - 2; i++) {
            c = 1.0f / (4.0f - c);
            s_cp[i] = c;
        }
    }
    __syncthreads();

    for (int i = tid; i < N_FRAMES * NUM_COEFF; i += blockDim.x) {
        int r = i / NUM_COEFF, c = i % NUM_COEFF;
        s_y[1 + c][r] = 1.0f / (1.0f + expf(-raw_coeff[i]));
    }
    for (int r = tid; r < N_FRAMES; r += blockDim.x)
        s_y[0][r] = delay[r];
    __syncthreads();

    for (int r = tid; r < N_FRAMES; r += blockDim.x) {
        float sum = 0.0f;
        #pragma unroll
        for (int c = 0; c < NUM_COEFF; c++) sum += s_y[1 + c][r];
        float scale = s_gain / sum;
        #pragma unroll
        for (int c = 0; c < NUM_COEFF; c++) s_y[1 + c][r] *= scale;
    }
    __syncthreads();

    if (tid < NSER) {
        const int m = N_FRAMES - 2;
        const float K = 6.0f * 127.0f * 127.0f;
        float* y = s_y[tid];
        float* d = s_d[tid];

        float dp = K * (y[2] - 2.0f * y[1] + y[0]) * 0.25f;
        d[0] = dp;
        for (int i = 1; i < m; i++) {
            float rhs = K * (y[i + 2] - 2.0f * y[i + 1] + y[i]);
            dp = (rhs - dp) * s_cp[i];
            d[i] = dp;
        }
        g_M[tid][0] = 0.0f;
        g_M[tid][N_FRAMES - 1] = 0.0f;
        float Mn = 0.0f;
        for (int i = m - 1; i >= 0; i--) {
            Mn = d[i] - s_cp[i] * Mn;
            g_M[tid][i + 1] = Mn;
        }
    }
    __syncthreads();

    for (int i = tid; i < NSER * N_FRAMES; i += blockDim.x)
        (&g_y[0][0])[i] = (&s_y[0][0])[i];
}

// ---------------- kernel B: per-sample spline eval + tap weights ----------------
__global__ void sample_kernel(const float* __restrict__ exc,
                              const float* __restrict__ burst)
{
    const int t = blockIdx.x * blockDim.x + threadIdx.x;
    if (t >= N_SAMPLES) return;

    const float tt = (float)t * (1.0f / 65535.0f);
    int idx = (int)floorf(tt * 127.0f);
    idx = max(0, min(idx, 126));
    const float s  = tt - (float)idx * (1.0f / 127.0f);
    const float s2 = s * s;
    const float s3 = s2 * s;

    float vout[NSER];
    #pragma unroll
    for (int c = 0; c < NSER; c++) {
        float yi  = g_y[c][idx];
        float yi1 = g_y[c][idx + 1];
        float Mi  = g_M[c][idx];
        float Mi1 = g_M[c][idx + 1];
        float bsl = (yi1 - yi) * 127.0f - (2.0f * Mi + Mi1) * (1.0f / 762.0f);
        vout[c] = yi + bsl * s + 0.5f * Mi * s2 + (Mi1 - Mi) * s3 * (127.0f / 6.0f);
    }

    const float delay_i = vout[0];
    const int   z    = (int)floorf(delay_i);
    const float alfa = delay_i - (float)z;
    const float oma  = 1.0f - alfa;

    float v[7];
    v[0] = -oma * vout[1];
    #pragma unroll
    for (int k = 1; k < NUM_COEFF; k++)
        v[k] = -(alfa * vout[k] + oma * vout[k + 1]);
    v[6] = -alfa * vout[NUM_COEFF];

    g_AB[2 * t]     = make_float4(v[0], v[1], v[2], v[3]);
    g_AB[2 * t + 1] = make_float4(v[4], v[5], v[6], burst[t]);
    g_P[t] = t - 1 - z;

    if (exc[t] != 0.0f) atomicExch(&g_flag, 1);

    int wmin = __reduce_min_sync(0xffffffffu, z);
    int wmax = __reduce_max_sync(0xffffffffu, z);
    if ((threadIdx.x & 31) == 0) {
        atomicMin(&g_minz, wmin);
        atomicMax(&g_maxz, wmax);
    }
}

// ---------------- kernel B2: general exc IIR fallback ----------------
__global__ void exc_scan_kernel(const float* __restrict__ exc,
                                const float* __restrict__ burst)
{
    if (g_flag) {
        float ym1 = 0.0f;
        for (int t = 0; t < N_SAMPLES; t++) {
            ym1 = burst[t] - exc[t] * ym1;
            g_AB[2 * t + 1].w = ym1;
        }
    }
}

// ---------------- helpers: release/acquire on shared progress counter ------
__device__ __forceinline__ void prog_store_release(int* p, int v) {
    asm volatile("st.release.cta.shared::cta.b32 [%0], %1;"
                 :: "l"((size_t)__cvta_generic_to_shared(p)), "r"(v) : "memory");
}
__device__ __forceinline__ int prog_load_acquire(int* p) {
    int v;
    asm volatile("ld.acquire.cta.shared::cta.b32 %0, [%1];"
                 : "=r"(v) : "l"((size_t)__cvta_generic_to_shared(p)) : "memory");
    return v;
}

// ---------------- kernel C: warp-specialized Karplus-Strong scan -----------
// Warp 0 (consumer): serial chunked scan, each lane owns up to 4 samples of
//   the L-sample chunk (samples within a chunk are independent: lag >= L).
//   Ring is DUPLICATED (slot s and s+1024) so the 7 taps of a sample are 7
//   LDS at immediate offsets from one base: base2 = (pb & 1023) + 1024.
//   Payload (taps, x, pb) is register-pipelined DEPTH=3 chunks ahead.
// Warp 1 (follower): trails the consumer via an acquire/release progress
//   counter and drains ring -> out[] with STG, off the critical path.
// Safety: distinct positions p != q share a ring slot only if p==q mod 1024;
//   read/write positions within an iteration differ by < 434, and follower
//   lag stays far below 1024 - (maxz + 7 + L).
__global__ void __launch_bounds__(64, 1) ks_kernel(float* __restrict__ out)
{
    __shared__ float ring[2048];
    __shared__ int   sL;
    __shared__ int   s_prog;

    const int tid = threadIdx.x;
    #pragma unroll
    for (int i = tid; i < 2048; i += 64) ring[i] = 0.0f;

    if (tid == 0) {
        int L = g_minz + 1;
        if (L > 128) L = 128;
        int cap = 1024 - (g_maxz + NUM_ACTIVE) - 1;
        if (L > cap) L = cap;
        if (L < 1)  L = 1;
        sL = L;
        s_prog = 0;
    }
    __syncthreads();
    const int L = sL;
    const int nChunks = (N_SAMPLES + L - 1) / L;

    if (tid < 32) {
        // ================= consumer warp =================
        const int l = tid;
        bool act[4];
        #pragma unroll
        for (int k = 0; k < 4; k++) act[k] = (l + 32 * k) < L;

        float4 A[DEPTH][4], B[DEPTH][4];
        int    P[DEPTH][4];

        // preload chunks 0..DEPTH-1
        #pragma unroll
        for (int s = 0; s < DEPTH; s++) {
            #pragma unroll
            for (int k = 0; k < 4; k++) {
                A[s][k] = make_float4(0, 0, 0, 0);
                B[s][k] = make_float4(0, 0, 0, 0);
                P[s][k] = 0;
                int t = s * L + l + 32 * k;
                if (act[k]) {                 // t < 65536 always here
                    A[s][k] = g_AB[2 * t];
                    B[s][k] = g_AB[2 * t + 1];
                    P[s][k] = g_P[t];
                }
            }
        }

        int tc = 0;                            // = chunk_index * L
        for (int c = 0; c < nChunks; c += DEPTH) {
            #pragma unroll
            for (int s = 0; s < DEPTH; s++) {
                const int cc = c + s;
                const int tpref = tc + DEPTH * L;   // chunk cc+DEPTH base

                // compute chunk cc
                if (cc < nChunks) {
                    #pragma unroll
                    for (int k = 0; k < 4; k++) {
                        const int t = tc + l + 32 * k;
                        if (act[k] && t < N_SAMPLES) {
                            const float4 a = A[s][k];
                            const float4 b = B[s][k];
                            const int base2 = (P[s][k] & 1023) + 1024;
                            float r0 = ring[base2];
                            float r1 = ring[base2 - 1];
                            float r2 = ring[base2 - 2];
                            float r3 = ring[base2 - 3];
                            float r4 = ring[base2 - 4];
                            float r5 = ring[base2 - 5];
                            float r6 = ring[base2 - 6];
                            float m0 = fmaf(a.x, r0, a.y * r1);
                            float m1 = fmaf(a.z, r2, a.w * r3);
                            float m2 = fmaf(b.x, r4, b.y * r5);
                            float m3 = b.z * r6;
                            float y  = b.w - ((m0 + m1) + (m2 + m3));
                            const int slot = t & 1023;
                            ring[slot] = y;
                            ring[slot + 1024] = y;
                        }
                    }
                }

                // prefetch chunk cc+DEPTH into buffer s
                #pragma unroll
                for (int k = 0; k < 4; k++) {
                    const int tp = tpref + l + 32 * k;
                    if (act[k] && tp < N_SAMPLES) {
                        A[s][k] = g_AB[2 * tp];
                        B[s][k] = g_AB[2 * tp + 1];
                        P[s][k] = g_P[tp];
                    }
                }

                __syncwarp();
                if (cc < nChunks && l == 0)
                    prog_store_release(&s_prog, cc + 1);
                tc += L;
            }
        }
    } else {
        // ================= follower warp: ring -> out =================
        const int l = tid - 32;
        int tc = 0;
        for (int c = 0; c < nChunks; c++) {
            int spin = 0;
            while (prog_load_acquire(&s_prog) <= c) {
                if (++spin > 32) { __nanosleep(60); spin = 0; }
            }
            #pragma unroll
            for (int k = 0; k < 4; k++) {
                const int t = tc + l + 32 * k;
                if ((l + 32 * k) < L && t < N_SAMPLES)
                    out[t] = ring[t & 1023];
            }
            tc += L;
        }
    }
}

// ---------------- launcher ----------------
extern "C" void kernel_launch(void* const* d_in, const int* in_sizes, int n_in,
                              void* d_out, int out_size)
{
    const float* delay     = (const float*)d_in[0];  // [128]
    const float* raw_gain  = (const float*)d_in[1];  // [1]
    const float* raw_coeff = (const float*)d_in[2];  // [128,6]
    const float* exc       = (const float*)d_in[3];  // [1,65536,1]
    const float* burst     = (const float*)d_in[4];  // [65536]
    float* out = (float*)d_out;

    prep_kernel<<<1, 256>>>(delay, raw_gain, raw_coeff);
    sample_kernel<<<N_SAMPLES / 256, 256>>>(exc, burst);
    exc_scan_kernel<<<1, 1>>>(exc, burst);
    ks_kernel<<<1, 64>>>(out);
}

// round 5
// speedup vs baseline: 2.2745x; 2.2745x over previous
#include <cuda_runtime.h>
#include <math.h>

#define N_SAMPLES   65536
#define N_FRAMES    128
#define NUM_COEFF   6
#define NUM_ACTIVE  7
#define NSER        7
#define DEPTH       4        // payload pipeline depth (chunks in flight)

// ---------------- device scratch (no allocation allowed) ----------------
__device__ float  g_y[NSER][N_FRAMES];
__device__ float  g_M[NSER][N_FRAMES];
__device__ float4 g_A[N_SAMPLES];        // taps v0..v3 (pre-negated)
__device__ float4 g_B[N_SAMPLES];        // taps v4,v5,v6, x
__device__ int    g_P[N_SAMPLES];        // ((t-1-z) & 1023) + 1024  (ring base, high copy)
__device__ int    g_minz;
__device__ int    g_maxz;
__device__ int    g_flag;

// ---------------- kernel A: coeff frames + spline tridiagonal solves ----------------
__global__ void prep_kernel(const float* __restrict__ delay,
                            const float* __restrict__ raw_gain,
                            const float* __restrict__ raw_coeff)
{
    __shared__ float s_y[NSER][N_FRAMES];
    __shared__ float s_cp[N_FRAMES];
    __shared__ float s_d[NSER][N_FRAMES];
    __shared__ float s_gain;

    const int tid = threadIdx.x;

    if (tid == 0) {
        s_gain = 1.0f / (1.0f + expf(-raw_gain[0]));
        g_minz = 0x7fffffff;
        g_maxz = 0;
        g_flag = 0;
        float c = 0.25f;
        s_cp[0] = c;
        for (int i = 1; i < N_FRAMES - 2; i++) {
            c = 1.0f / (4.0f - c);
            s_cp[i] = c;
        }
    }
    __syncthreads();

    for (int i = tid; i < N_FRAMES * NUM_COEFF; i += blockDim.x) {
        int r = i / NUM_COEFF, c = i % NUM_COEFF;
        s_y[1 + c][r] = 1.0f / (1.0f + expf(-raw_coeff[i]));
    }
    for (int r = tid; r < N_FRAMES; r += blockDim.x)
        s_y[0][r] = delay[r];
    __syncthreads();

    for (int r = tid; r < N_FRAMES; r += blockDim.x) {
        float sum = 0.0f;
        #pragma unroll
        for (int c = 0; c < NUM_COEFF; c++) sum += s_y[1 + c][r];
        float scale = s_gain / sum;
        #pragma unroll
        for (int c = 0; c < NUM_COEFF; c++) s_y[1 + c][r] *= scale;
    }
    __syncthreads();

    if (tid < NSER) {
        const int m = N_FRAMES - 2;
        const float K = 6.0f * 127.0f * 127.0f;
        float* y = s_y[tid];
        float* d = s_d[tid];

        float dp = K * (y[2] - 2.0f * y[1] + y[0]) * 0.25f;
        d[0] = dp;
        for (int i = 1; i < m; i++) {
            float rhs = K * (y[i + 2] - 2.0f * y[i + 1] + y[i]);
            dp = (rhs - dp) * s_cp[i];
            d[i] = dp;
        }
        g_M[tid][0] = 0.0f;
        g_M[tid][N_FRAMES - 1] = 0.0f;
        float Mn = 0.0f;
        for (int i = m - 1; i >= 0; i--) {
            Mn = d[i] - s_cp[i] * Mn;
            g_M[tid][i + 1] = Mn;
        }
    }
    __syncthreads();

    for (int i = tid; i < NSER * N_FRAMES; i += blockDim.x)
        (&g_y[0][0])[i] = (&s_y[0][0])[i];
}

// ---------------- kernel B: per-sample spline eval + tap weights ----------------
__global__ void sample_kernel(const float* __restrict__ exc,
                              const float* __restrict__ burst)
{
    const int t = blockIdx.x * blockDim.x + threadIdx.x;
    if (t >= N_SAMPLES) return;

    const float tt = (float)t * (1.0f / 65535.0f);
    int idx = (int)floorf(tt * 127.0f);
    idx = max(0, min(idx, 126));
    const float s  = tt - (float)idx * (1.0f / 127.0f);
    const float s2 = s * s;
    const float s3 = s2 * s;

    float vout[NSER];
    #pragma unroll
    for (int c = 0; c < NSER; c++) {
        float yi  = g_y[c][idx];
        float yi1 = g_y[c][idx + 1];
        float Mi  = g_M[c][idx];
        float Mi1 = g_M[c][idx + 1];
        float bsl = (yi1 - yi) * 127.0f - (2.0f * Mi + Mi1) * (1.0f / 762.0f);
        vout[c] = yi + bsl * s + 0.5f * Mi * s2 + (Mi1 - Mi) * s3 * (127.0f / 6.0f);
    }

    const float delay_i = vout[0];
    const int   z    = (int)floorf(delay_i);
    const float alfa = delay_i - (float)z;
    const float oma  = 1.0f - alfa;

    float v[7];
    v[0] = -oma * vout[1];
    #pragma unroll
    for (int k = 1; k < NUM_COEFF; k++)
        v[k] = -(alfa * vout[k] + oma * vout[k + 1]);
    v[6] = -alfa * vout[NUM_COEFF];

    g_A[t] = make_float4(v[0], v[1], v[2], v[3]);
    g_B[t] = make_float4(v[4], v[5], v[6], burst[t]);  // .w = x
    g_P[t] = ((t - 1 - z) & 1023) + 1024;              // ready-to-use LDS base

    if (exc[t] != 0.0f) atomicExch(&g_flag, 1);

    int wmin = __reduce_min_sync(0xffffffffu, z);
    int wmax = __reduce_max_sync(0xffffffffu, z);
    if ((threadIdx.x & 31) == 0) {
        atomicMin(&g_minz, wmin);
        atomicMax(&g_maxz, wmax);
    }
}

// ---------------- kernel B2: general exc IIR fallback ----------------
__global__ void exc_scan_kernel(const float* __restrict__ exc,
                                const float* __restrict__ burst)
{
    if (g_flag) {
        float ym1 = 0.0f;
        for (int t = 0; t < N_SAMPLES; t++) {
            ym1 = burst[t] - exc[t] * ym1;
            g_B[t].w = ym1;
        }
    }
}

// ---------------- kernel C: chunk-parallel Karplus-Strong scan -------------
// 4 warps / 128 threads, one sample per thread per chunk; depth-4 register
// pipeline on the payload (memory latency fully covered).
// DUPLICATED ring: each y is written to slot s=t&1023 and s+1024; readers use
// the precomputed base P2 = ((t-1-z)&1023)+1024 and take 7 LDS at immediate
// offsets (base-0..base-6).  Low-copy reads near the seam (base-k < 1024)
// return the identical value; slots never written yet are zero in both
// copies, and the R2 aliasing argument (j<0 maps to slots first written at
// t>=704, read last before t=321) carries over unchanged.
__global__ void __launch_bounds__(128, 1) ks_kernel(float* __restrict__ out)
{
    __shared__ float ring[2048];
    __shared__ int   sL;

    const int tid = threadIdx.x;
    #pragma unroll
    for (int i = tid; i < 2048; i += 128) ring[i] = 0.0f;

    if (tid == 0) {
        int L = g_minz + 1;                          // dependency lag bound
        if (L > 128) L = 128;
        int cap = 1024 - (g_maxz + NUM_ACTIVE) - 1;  // ring disjointness
        if (L > cap) L = cap;
        if (L < 1)  L = 1;
        sL = L;
    }
    __syncthreads();
    const int  L  = sL;
    const int  LD = DEPTH * L;
    const bool on = (tid < L);

    float4 A[DEPTH], B[DEPTH];
    int    P[DEPTH];
    #pragma unroll
    for (int s = 0; s < DEPTH; s++) {
        A[s] = make_float4(0, 0, 0, 0);
        B[s] = make_float4(0, 0, 0, 0);
        P[s] = 1024;
        if (on) {
            A[s] = g_A[tid + s * L];
            B[s] = g_B[tid + s * L];
            P[s] = g_P[tid + s * L];
        }
    }

    // register-maintained ring slot and output pointer (no per-iter IMADs)
    int    slot = tid & 1023;
    float* outp = out + tid;

    for (int t0 = 0; t0 < N_SAMPLES; t0 += LD) {
        #pragma unroll
        for (int s = 0; s < DEPTH; s++) {
            const int t = t0 + s * L + tid;
            const float4 a  = A[s];
            const float4 b  = B[s];
            const int    pb = P[s];

            const int tp = t + LD;                  // prefetch DEPTH chunks ahead
            if (on && tp < N_SAMPLES) {
                A[s] = g_A[tp]; B[s] = g_B[tp]; P[s] = g_P[tp];
            }

            if (on && t < N_SAMPLES) {
                float r0 = ring[pb    ];
                float r1 = ring[pb - 1];
                float r2 = ring[pb - 2];
                float r3 = ring[pb - 3];
                float r4 = ring[pb - 4];
                float r5 = ring[pb - 5];
                float r6 = ring[pb - 6];
                float m0 = fmaf(a.x, r0, a.y * r1);
                float m1 = fmaf(a.z, r2, a.w * r3);
                float m2 = fmaf(b.x, r4, b.y * r5);
                float m3 = b.z * r6;
                float y  = b.w - ((m0 + m1) + (m2 + m3));
                ring[slot]        = y;
                ring[slot + 1024] = y;
                *outp = y;
            }
            __syncthreads();

            slot = (slot + L) & 1023;
            outp += L;
        }
    }
}

// ---------------- launcher ----------------
extern "C" void kernel_launch(void* const* d_in, const int* in_sizes, int n_in,
                              void* d_out, int out_size)
{
    const float* delay     = (const float*)d_in[0];  // [128]
    const float* raw_gain  = (const float*)d_in[1];  // [1]
    const float* raw_coeff = (const float*)d_in[2];  // [128,6]
    const float* exc       = (const float*)d_in[3];  // [1,65536,1]
    const float* burst     = (const float*)d_in[4];  // [65536]
    float* out = (float*)d_out;

    prep_kernel<<<1, 256>>>(delay, raw_gain, raw_coeff);
    sample_kernel<<<N_SAMPLES / 256, 256>>>(exc, burst);
    exc_scan_kernel<<<1, 1>>>(exc, burst);
    ks_kernel<<<1, 128>>>(out);
}

// round 6
// speedup vs baseline: 2.5274x; 1.1112x over previous
#include <cuda_runtime.h>
#include <math.h>

#define N_SAMPLES   65536
#define N_FRAMES    128
#define NUM_COEFF   6
#define NUM_ACTIVE  7
#define NSER        7
#define NSTAGE      5        // staging slots (4 cp.async groups in flight)

// ---------------- device scratch (no allocation allowed) ----------------
__device__ float  g_y[NSER][N_FRAMES];
__device__ float  g_M[NSER][N_FRAMES];
__device__ float4 g_A[N_SAMPLES];        // taps v0..v3 (pre-negated)
__device__ float4 g_B[N_SAMPLES];        // taps v4,v5,v6, x
__device__ int    g_P[N_SAMPLES];        // ((t-1-z) & 1023) + 1024  (ring base, high copy)
__device__ int    g_minz;
__device__ int    g_maxz;
__device__ int    g_flag;

// ---------------- kernel A: coeff frames + spline tridiagonal solves ----------------
__global__ void prep_kernel(const float* __restrict__ delay,
                            const float* __restrict__ raw_gain,
                            const float* __restrict__ raw_coeff)
{
    __shared__ float s_y[NSER][N_FRAMES];
    __shared__ float s_cp[N_FRAMES];
    __shared__ float s_d[NSER][N_FRAMES];
    __shared__ float s_gain;

    const int tid = threadIdx.x;

    if (tid == 0) {
        s_gain = 1.0f / (1.0f + expf(-raw_gain[0]));
        g_minz = 0x7fffffff;
        g_maxz = 0;
        g_flag = 0;
        float c = 0.25f;
        s_cp[0] = c;
        for (int i = 1; i < N_FRAMES - 2; i++) {
            c = 1.0f / (4.0f - c);
            s_cp[i] = c;
        }
    }
    __syncthreads();

    for (int i = tid; i < N_FRAMES * NUM_COEFF; i += blockDim.x) {
        int r = i / NUM_COEFF, c = i % NUM_COEFF;
        s_y[1 + c][r] = 1.0f / (1.0f + expf(-raw_coeff[i]));
    }
    for (int r = tid; r < N_FRAMES; r += blockDim.x)
        s_y[0][r] = delay[r];
    __syncthreads();

    for (int r = tid; r < N_FRAMES; r += blockDim.x) {
        float sum = 0.0f;
        #pragma unroll
        for (int c = 0; c < NUM_COEFF; c++) sum += s_y[1 + c][r];
        float scale = s_gain / sum;
        #pragma unroll
        for (int c = 0; c < NUM_COEFF; c++) s_y[1 + c][r] *= scale;
    }
    __syncthreads();

    if (tid < NSER) {
        const int m = N_FRAMES - 2;
        const float K = 6.0f * 127.0f * 127.0f;
        float* y = s_y[tid];
        float* d = s_d[tid];

        float dp = K * (y[2] - 2.0f * y[1] + y[0]) * 0.25f;
        d[0] = dp;
        for (int i = 1; i < m; i++) {
            float rhs = K * (y[i + 2] - 2.0f * y[i + 1] + y[i]);
            dp = (rhs - dp) * s_cp[i];
            d[i] = dp;
        }
        g_M[tid][0] = 0.0f;
        g_M[tid][N_FRAMES - 1] = 0.0f;
        float Mn = 0.0f;
        for (int i = m - 1; i >= 0; i--) {
            Mn = d[i] - s_cp[i] * Mn;
            g_M[tid][i + 1] = Mn;
        }
    }
    __syncthreads();

    for (int i = tid; i < NSER * N_FRAMES; i += blockDim.x)
        (&g_y[0][0])[i] = (&s_y[0][0])[i];
}

// ---------------- kernel B: per-sample spline eval + tap weights ----------------
__global__ void sample_kernel(const float* __restrict__ exc,
                              const float* __restrict__ burst)
{
    const int t = blockIdx.x * blockDim.x + threadIdx.x;
    if (t >= N_SAMPLES) return;

    const float tt = (float)t * (1.0f / 65535.0f);
    int idx = (int)floorf(tt * 127.0f);
    idx = max(0, min(idx, 126));
    const float s  = tt - (float)idx * (1.0f / 127.0f);
    const float s2 = s * s;
    const float s3 = s2 * s;

    float vout[NSER];
    #pragma unroll
    for (int c = 0; c < NSER; c++) {
        float yi  = g_y[c][idx];
        float yi1 = g_y[c][idx + 1];
        float Mi  = g_M[c][idx];
        float Mi1 = g_M[c][idx + 1];
        float bsl = (yi1 - yi) * 127.0f - (2.0f * Mi + Mi1) * (1.0f / 762.0f);
        vout[c] = yi + bsl * s + 0.5f * Mi * s2 + (Mi1 - Mi) * s3 * (127.0f / 6.0f);
    }

    const float delay_i = vout[0];
    const int   z    = (int)floorf(delay_i);
    const float alfa = delay_i - (float)z;
    const float oma  = 1.0f - alfa;

    float v[7];
    v[0] = -oma * vout[1];
    #pragma unroll
    for (int k = 1; k < NUM_COEFF; k++)
        v[k] = -(alfa * vout[k] + oma * vout[k + 1]);
    v[6] = -alfa * vout[NUM_COEFF];

    g_A[t] = make_float4(v[0], v[1], v[2], v[3]);
    g_B[t] = make_float4(v[4], v[5], v[6], burst[t]);  // .w = x
    g_P[t] = ((t - 1 - z) & 1023) + 1024;              // ready-to-use LDS base

    if (exc[t] != 0.0f) atomicExch(&g_flag, 1);

    int wmin = __reduce_min_sync(0xffffffffu, z);
    int wmax = __reduce_max_sync(0xffffffffu, z);
    if ((threadIdx.x & 31) == 0) {
        atomicMin(&g_minz, wmin);
        atomicMax(&g_maxz, wmax);
    }
}

// ---------------- kernel B2: general exc IIR fallback ----------------
__global__ void exc_scan_kernel(const float* __restrict__ exc,
                                const float* __restrict__ burst)
{
    if (g_flag) {
        float ym1 = 0.0f;
        for (int t = 0; t < N_SAMPLES; t++) {
            ym1 = burst[t] - exc[t] * ym1;
            g_B[t].w = ym1;
        }
    }
}

// ---------------- cp.async helpers ----------------
__device__ __forceinline__ void cpa16(void* dst_smem, const void* src) {
    unsigned d = (unsigned)__cvta_generic_to_shared(dst_smem);
    asm volatile("cp.async.ca.shared.global [%0], [%1], 16;"
                 :: "r"(d), "l"(src) : "memory");
}
__device__ __forceinline__ void cpa4(void* dst_smem, const void* src) {
    unsigned d = (unsigned)__cvta_generic_to_shared(dst_smem);
    asm volatile("cp.async.ca.shared.global [%0], [%1], 4;"
                 :: "r"(d), "l"(src) : "memory");
}

// ---------------- kernel C: chunk-parallel Karplus-Strong scan -------------
// 4 warps, one sample per thread per chunk. Payload (taps, x, ring base) is
// prefetched via cp.async (LDGSTS pipeline) into a 5-slot staging ring with
// 4 groups in flight, so NO register-destined LDG exists inside the loop —
// the only scoreboarded loads are short-latency LDS. This removes the wbar
// aliasing between deep-slack LDGs and critical ring LDS reads.
// Slot reuse is safe: slot written for chunk c+4 was last read at chunk c-1;
// that read's value was consumed (hence complete) before the __syncthreads
// preceding this cp.async issue.
// Ring duplication / index safety unchanged from R5.
__global__ void __launch_bounds__(128, 1) ks_kernel(float* __restrict__ out)
{
    __shared__ float  ring[2048];
    __shared__ float4 stA[NSTAGE][128];
    __shared__ float4 stB[NSTAGE][128];
    __shared__ int    stP[NSTAGE][128];
    __shared__ int    sL;

    const int tid = threadIdx.x;
    #pragma unroll
    for (int i = tid; i < 2048; i += 128) ring[i] = 0.0f;

    if (tid == 0) {
        int L = g_minz + 1;
        if (L > 128) L = 128;
        int cap = 1024 - (g_maxz + NUM_ACTIVE) - 1;
        if (L > cap) L = cap;
        if (L < 1)  L = 1;
        sL = L;
    }
    __syncthreads();
    const int  L  = sL;
    const bool on = (tid < L);
    const int  nChunks = (N_SAMPLES + L - 1) / L;

    // prologue: chunks 0..3 -> slots 0..3 (4 groups in flight)
    #pragma unroll
    for (int s = 0; s < NSTAGE - 1; s++) {
        const int t = s * L + tid;
        if (on) {                              // t < 65536 always here
            cpa16(&stA[s][tid], &g_A[t]);
            cpa16(&stB[s][tid], &g_B[t]);
            cpa4 (&stP[s][tid], &g_P[t]);
        }
        asm volatile("cp.async.commit_group;" ::: "memory");
    }

    int    slot = tid & 1023;                  // ring write slot (low copy)
    float* outp = out + tid;

    for (int c0 = 0; c0 < nChunks; c0 += NSTAGE) {
        #pragma unroll
        for (int s = 0; s < NSTAGE; s++) {
            const int c = c0 + s;
            if (c < nChunks) {
                // oldest outstanding group (chunk c, slot s) must be done
                asm volatile("cp.async.wait_group 3;" ::: "memory");

                const float4 a  = stA[s][tid];
                const float4 b  = stB[s][tid];
                const int    pb = stP[s][tid];

                // prefetch chunk c+4 into slot (s+4)%NSTAGE
                const int tp = (c + NSTAGE - 1) * L + tid;
                if (on && tp < N_SAMPLES) {
                    cpa16(&stA[(s + NSTAGE - 1) % NSTAGE][tid], &g_A[tp]);
                    cpa16(&stB[(s + NSTAGE - 1) % NSTAGE][tid], &g_B[tp]);
                    cpa4 (&stP[(s + NSTAGE - 1) % NSTAGE][tid], &g_P[tp]);
                }
                asm volatile("cp.async.commit_group;" ::: "memory");

                const int t = c * L + tid;
                if (on && t < N_SAMPLES) {
                    float r0 = ring[pb    ];
                    float r1 = ring[pb - 1];
                    float r2 = ring[pb - 2];
                    float r3 = ring[pb - 3];
                    float r4 = ring[pb - 4];
                    float r5 = ring[pb - 5];
                    float r6 = ring[pb - 6];
                    float m0 = fmaf(a.x, r0, a.y * r1);
                    float m1 = fmaf(a.z, r2, a.w * r3);
                    float m2 = fmaf(b.x, r4, b.y * r5);
                    float m3 = b.z * r6;
                    float y  = b.w - ((m0 + m1) + (m2 + m3));
                    ring[slot]        = y;
                    ring[slot + 1024] = y;
                    *outp = y;
                }
                __syncthreads();

                slot = (slot + L) & 1023;
                outp += L;
            }
        }
    }
}

// ---------------- launcher ----------------
extern "C" void kernel_launch(void* const* d_in, const int* in_sizes, int n_in,
                              void* d_out, int out_size)
{
    const float* delay     = (const float*)d_in[0];  // [128]
    const float* raw_gain  = (const float*)d_in[1];  // [1]
    const float* raw_coeff = (const float*)d_in[2];  // [128,6]
    const float* exc       = (const float*)d_in[3];  // [1,65536,1]
    const float* burst     = (const float*)d_in[4];  // [65536]
    float* out = (float*)d_out;

    prep_kernel<<<1, 256>>>(delay, raw_gain, raw_coeff);
    sample_kernel<<<N_SAMPLES / 256, 256>>>(exc, burst);
    exc_scan_kernel<<<1, 1>>>(exc, burst);
    ks_kernel<<<1, 128>>>(out);
}